// round 4
// baseline (speedup 1.0000x reference)
#include <cuda_runtime.h>
#include <cstdint>

#define NND 50000
#define NE  800000
#define DD  128

// ---- device scratch (static __device__ arrays are the sanctioned scratch) ----
__device__ int g_is32;
__device__ __align__(16) int   g_edge[2 * NE];           // canonical int32 edges (src | dst)
__device__ __align__(16) int   g_cnt[NND];               // in-degree (excl self-loop)
__device__ __align__(16) int   g_off[NND];               // CSR offsets
__device__ __align__(16) int   g_cur[NND];               // placement cursors
__device__ __align__(16) int   g_srcl[NE];               // CSR src lists
__device__ __align__(16) float g_xs[(size_t)NND * DD];   // (x@Wc) * dinv[row]
__device__ __align__(16) float g_acc[(size_t)NND * DD];  // gathered sums (incl self)
__device__ __align__(16) float g_Wt2[DD * DD];           // Wt + I
__device__ __align__(16) float g_Wx[DD * DD];            // W0 - Wt

// ---------------------------------------------------------------------------
// K-1: detect edge_index dtype (int32 vs int64) from data values.
// int64 interpretation of int32 data yields values with a nonzero high word
// (high word = a random node id, zero with prob ~2e-5) -> out of [0, NND).
// ---------------------------------------------------------------------------
__global__ void detect_kernel(const void* __restrict__ ei, int n_elems) {
    if (threadIdx.x == 0 && blockIdx.x == 0) {
        const long long* p = (const long long*)ei;
        int is32 = 0;
        #pragma unroll 1
        for (int i = 0; i < 64; i++) {
            long long v = p[i];
            if (v < 0 || v >= NND) is32 = 1;
        }
        // if the buffer only has n_elems int32 words, it cannot hold 2*NE int64
        if (n_elems < 2 * NE * 2) is32 = 1;   // n_elems is elem count per metadata
        g_is32 = is32;
    }
}

// ---------------------------------------------------------------------------
// K0: canonicalize edges to int32 (clamped), fold weights, zero histogram
// ---------------------------------------------------------------------------
__global__ void convert_kernel(const void* __restrict__ ei) {
    int i = blockIdx.x * blockDim.x + threadIdx.x;
    const int is32 = g_is32;
    if (i < 2 * NE) {
        int v = is32 ? ((const int*)ei)[i] : (int)((const long long*)ei)[i];
        v = min(max(v, 0), NND - 1);   // defensive clamp: wrong guess -> wrong answer, not crash
        g_edge[i] = v;
    }
}

__global__ void prep_kernel(const float* __restrict__ W0, const float* __restrict__ Wt) {
    int i = blockIdx.x * blockDim.x + threadIdx.x;
    if (i < DD * DD) {
        float wt = Wt[i];
        g_Wt2[i] = wt + (((i >> 7) == (i & 127)) ? 1.0f : 0.0f);
        g_Wx[i]  = W0[i] - wt;
    }
    if (i < NND) g_cnt[i] = 0;
}

// ---------------------------------------------------------------------------
// K1: dst histogram (int atomics, spread addresses)
// ---------------------------------------------------------------------------
__global__ void hist_kernel() {
    int e = blockIdx.x * blockDim.x + threadIdx.x;
    if (e < NE) atomicAdd(&g_cnt[g_edge[NE + e]], 1);
}

// ---------------------------------------------------------------------------
// K2: exclusive scan of g_cnt -> g_off, g_cur  (single block, 1024 threads)
// ---------------------------------------------------------------------------
__global__ __launch_bounds__(1024) void scan_kernel() {
    __shared__ int ssum[1024];
    const int t = threadIdx.x;
    const int CH = (NND + 1023) / 1024;  // 49
    int b = t * CH, e = min(b + CH, NND);
    int s = 0;
    for (int i = b; i < e; i++) s += g_cnt[i];
    ssum[t] = s;
    __syncthreads();
    for (int off = 1; off < 1024; off <<= 1) {
        int v = (t >= off) ? ssum[t - off] : 0;
        __syncthreads();
        ssum[t] += v;
        __syncthreads();
    }
    int excl = (t == 0) ? 0 : ssum[t - 1];
    for (int i = b; i < e; i++) {
        g_off[i] = excl;
        g_cur[i] = excl;
        excl += g_cnt[i];
    }
}

// ---------------------------------------------------------------------------
// K3: place edges into CSR
// ---------------------------------------------------------------------------
__global__ void place_kernel() {
    int e = blockIdx.x * blockDim.x + threadIdx.x;
    if (e < NE) {
        int s = g_edge[e];
        int d = g_edge[NE + e];
        int pos = atomicAdd(&g_cur[d], 1);
        g_srcl[pos] = s;
    }
}

// ---------------------------------------------------------------------------
// GEMM building block: 256 threads, 128x128 output tile, K processed in two
// 64-wide halves staged transposed in 34KB static smem; W read via __ldg.
// ---------------------------------------------------------------------------
#define FMA8x8(a0, a1, b0, b1)                                                  \
    {                                                                           \
        float a[8] = {a0.x, a0.y, a0.z, a0.w, a1.x, a1.y, a1.z, a1.w};          \
        float b[8] = {b0.x, b0.y, b0.z, b0.w, b1.x, b1.y, b1.z, b1.w};          \
        _Pragma("unroll")                                                       \
        for (int i_ = 0; i_ < 8; i_++)                                          \
            _Pragma("unroll")                                                   \
            for (int j_ = 0; j_ < 8; j_++)                                      \
                acc[i_][j_] = fmaf(a[i_], b[j_], acc[i_][j_]);                  \
    }

// ---------------------------------------------------------------------------
// K4: xs = (x @ Wc) * dinv[row]
// ---------------------------------------------------------------------------
__global__ __launch_bounds__(256) void gemm_xw_kernel(const float* __restrict__ x,
                                                      const float* __restrict__ Wc) {
    __shared__ float inT[64][132];  // [k][row], 33792 B
    const int tid  = threadIdx.x;
    const int row0 = blockIdx.x << 7;
    const int tx = tid & 15, ty = tid >> 4;

    float acc[8][8];
    #pragma unroll
    for (int i = 0; i < 8; i++)
        #pragma unroll
        for (int j = 0; j < 8; j++) acc[i][j] = 0.0f;

    for (int kh = 0; kh < DD; kh += 64) {
        __syncthreads();
        for (int idx = tid; idx < 128 * 64; idx += 256) {
            int r = idx >> 6, c = idx & 63;      // coalesced over c
            int gr = row0 + r;
            inT[c][r] = (gr < NND) ? x[(size_t)gr * DD + kh + c] : 0.0f;
        }
        __syncthreads();
        #pragma unroll 8
        for (int k = 0; k < 64; k++) {
            float4 b0 = __ldg((const float4*)&Wc[(size_t)(kh + k) * DD + (tx << 3)]);
            float4 b1 = __ldg((const float4*)&Wc[(size_t)(kh + k) * DD + (tx << 3) + 4]);
            float4 a0 = *(const float4*)&inT[k][(ty << 3)];
            float4 a1 = *(const float4*)&inT[k][(ty << 3) + 4];
            FMA8x8(a0, a1, b0, b1)
        }
    }

    #pragma unroll
    for (int i = 0; i < 8; i++) {
        int gr = row0 + (ty << 3) + i;
        if (gr < NND) {
            float s = rsqrtf((float)(g_cnt[gr] + 1));
            size_t off = (size_t)gr * DD + (tx << 3);
            *(float4*)&g_xs[off]     = make_float4(acc[i][0]*s, acc[i][1]*s, acc[i][2]*s, acc[i][3]*s);
            *(float4*)&g_xs[off + 4] = make_float4(acc[i][4]*s, acc[i][5]*s, acc[i][6]*s, acc[i][7]*s);
        }
    }
}

// ---------------------------------------------------------------------------
// K5: gather — warp per node; acc[node] = xs[node] + sum_{s in N_in(node)} xs[s]
// ---------------------------------------------------------------------------
__global__ __launch_bounds__(256) void gather_kernel() {
    const int lane = threadIdx.x & 31;
    int warp = (blockIdx.x * blockDim.x + threadIdx.x) >> 5;
    const int nw = (gridDim.x * blockDim.x) >> 5;
    const int c = lane << 2;

    for (int node = warp; node < NND; node += nw) {
        const int off = g_off[node];
        const int cnt = g_cnt[node];
        float4 a = *(const float4*)&g_xs[(size_t)node * DD + c];  // self-loop term
        int j = 0;
        for (; j + 2 <= cnt; j += 2) {
            int s0 = g_srcl[off + j];
            int s1 = g_srcl[off + j + 1];
            float4 v0 = *(const float4*)&g_xs[(size_t)s0 * DD + c];
            float4 v1 = *(const float4*)&g_xs[(size_t)s1 * DD + c];
            a.x += v0.x + v1.x; a.y += v0.y + v1.y;
            a.z += v0.z + v1.z; a.w += v0.w + v1.w;
        }
        if (j < cnt) {
            int s0 = g_srcl[off + j];
            float4 v0 = *(const float4*)&g_xs[(size_t)s0 * DD + c];
            a.x += v0.x; a.y += v0.y; a.z += v0.z; a.w += v0.w;
        }
        *(float4*)&g_acc[(size_t)node * DD + c] = a;
    }
}

// ---------------------------------------------------------------------------
// K6: h = dinv*acc + bc ;  out = h @ (I+Wt) + x @ (W0-Wt)
// ---------------------------------------------------------------------------
__global__ __launch_bounds__(256) void final_kernel(const float* __restrict__ x,
                                                    const float* __restrict__ bc,
                                                    float* __restrict__ out) {
    __shared__ float inT[64][132];
    __shared__ float dinvs[128];
    const int tid  = threadIdx.x;
    const int row0 = blockIdx.x << 7;
    const int tx = tid & 15, ty = tid >> 4;

    if (tid < 128) {
        int gr = row0 + tid;
        dinvs[tid] = (gr < NND) ? rsqrtf((float)(g_cnt[gr] + 1)) : 0.0f;
    }

    float acc[8][8];
    #pragma unroll
    for (int i = 0; i < 8; i++)
        #pragma unroll
        for (int j = 0; j < 8; j++) acc[i][j] = 0.0f;

    // ---- phase 1: h @ (I + Wt),  h = dinv*acc + bc ----
    for (int kh = 0; kh < DD; kh += 64) {
        __syncthreads();
        for (int idx = tid; idx < 128 * 64; idx += 256) {
            int r = idx >> 6, c = idx & 63;
            int gr = row0 + r;
            float h = 0.0f;
            if (gr < NND)
                h = g_acc[(size_t)gr * DD + kh + c] * dinvs[r] + __ldg(&bc[kh + c]);
            inT[c][r] = h;
        }
        __syncthreads();
        #pragma unroll 8
        for (int k = 0; k < 64; k++) {
            float4 b0 = __ldg((const float4*)&g_Wt2[(size_t)(kh + k) * DD + (tx << 3)]);
            float4 b1 = __ldg((const float4*)&g_Wt2[(size_t)(kh + k) * DD + (tx << 3) + 4]);
            float4 a0 = *(const float4*)&inT[k][(ty << 3)];
            float4 a1 = *(const float4*)&inT[k][(ty << 3) + 4];
            FMA8x8(a0, a1, b0, b1)
        }
    }

    // ---- phase 2: + x @ (W0 - Wt) ----
    for (int kh = 0; kh < DD; kh += 64) {
        __syncthreads();
        for (int idx = tid; idx < 128 * 64; idx += 256) {
            int r = idx >> 6, c = idx & 63;
            int gr = row0 + r;
            inT[c][r] = (gr < NND) ? x[(size_t)gr * DD + kh + c] : 0.0f;
        }
        __syncthreads();
        #pragma unroll 8
        for (int k = 0; k < 64; k++) {
            float4 b0 = __ldg((const float4*)&g_Wx[(size_t)(kh + k) * DD + (tx << 3)]);
            float4 b1 = __ldg((const float4*)&g_Wx[(size_t)(kh + k) * DD + (tx << 3) + 4]);
            float4 a0 = *(const float4*)&inT[k][(ty << 3)];
            float4 a1 = *(const float4*)&inT[k][(ty << 3) + 4];
            FMA8x8(a0, a1, b0, b1)
        }
    }

    #pragma unroll
    for (int i = 0; i < 8; i++) {
        int gr = row0 + (ty << 3) + i;
        if (gr < NND) {
            size_t off = (size_t)gr * DD + (tx << 3);
            *(float4*)&out[off]     = make_float4(acc[i][0], acc[i][1], acc[i][2], acc[i][3]);
            *(float4*)&out[off + 4] = make_float4(acc[i][4], acc[i][5], acc[i][6], acc[i][7]);
        }
    }
}

// ---------------------------------------------------------------------------
extern "C" void kernel_launch(void* const* d_in, const int* in_sizes, int n_in,
                              void* d_out, int out_size) {
    const float* x  = (const float*)d_in[0];
    const void*  ei = d_in[1];
    const float* Wc = (const float*)d_in[2];
    const float* bc = (const float*)d_in[3];
    const float* W0 = (const float*)d_in[4];
    const float* Wt = (const float*)d_in[5];
    float* out = (float*)d_out;

    const int gemm_blocks = (NND + 127) / 128;  // 391

    detect_kernel<<<1, 32>>>(ei, in_sizes[1]);
    convert_kernel<<<(2 * NE + 255) / 256, 256>>>(ei);
    prep_kernel<<<(NND + 255) / 256, 256>>>(W0, Wt);
    hist_kernel<<<(NE + 255) / 256, 256>>>();
    scan_kernel<<<1, 1024>>>();
    place_kernel<<<(NE + 255) / 256, 256>>>();
    gemm_xw_kernel<<<gemm_blocks, 256>>>(x, Wc);
    gather_kernel<<<2048, 256>>>();
    final_kernel<<<gemm_blocks, 256>>>(x, bc, out);
}

// round 8
// speedup vs baseline: 1.5852x; 1.5852x over previous
#include <cuda_runtime.h>
#include <cuda_bf16.h>
#include <cstdint>

#define NND 50000
#define NE  800000
#define DD  128

#define SA      136                 // smem row stride in bf16 elems
#define TILEB   34816               // 128*136*2 bytes per bf16 tile buffer
#define NV4     2176                // TILEB/16

// ---- device scratch ----
__device__ int g_is32;
__device__ __align__(16) int   g_edge[2 * NE];
__device__ __align__(16) int   g_cnt[NND];
__device__ __align__(16) int   g_off[NND];
__device__ __align__(16) int   g_cur[NND];
__device__ __align__(16) int   g_srcl[NE];
__device__ __align__(16) float g_xs[(size_t)NND * DD];
__device__ __align__(16) float g_acc[(size_t)NND * DD];
// weights pre-transposed to B[n][k] = W[k][n], bf16 hi/lo split, stride SA
__device__ __align__(16) unsigned char gWcH[TILEB],  gWcL[TILEB];
__device__ __align__(16) unsigned char gWt2H[TILEB], gWt2L[TILEB];
__device__ __align__(16) unsigned char gWxH[TILEB],  gWxL[TILEB];

// ===================== PTX wrappers (all baseline, no 'a' features) =========
__device__ __forceinline__ uint32_t smem_u32(const void* p) {
    uint32_t a;
    asm("{ .reg .u64 t; cvta.to.shared.u64 t, %1; cvt.u32.u64 %0, t; }" : "=r"(a) : "l"(p));
    return a;
}
#define LDSM_X4(r, a)                                                           \
    asm volatile("ldmatrix.sync.aligned.m8n8.x4.shared.b16 {%0,%1,%2,%3}, [%4];"\
        : "=r"((r)[0]), "=r"((r)[1]), "=r"((r)[2]), "=r"((r)[3]) : "r"(a))
#define MMA16816(d, a, b)                                                       \
    asm volatile("mma.sync.aligned.m16n8k16.row.col.f32.bf16.bf16.f32 "         \
        "{%0,%1,%2,%3}, {%4,%5,%6,%7}, {%8,%9}, {%0,%1,%2,%3};"                 \
        : "+f"((d)[0]), "+f"((d)[1]), "+f"((d)[2]), "+f"((d)[3])                \
        : "r"((a)[0]), "r"((a)[1]), "r"((a)[2]), "r"((a)[3]),                   \
          "r"((b)[0]), "r"((b)[1]))

// split fp32x4 -> bf16 hi/lo, store 4 elems at (r, c), c % 4 == 0, stride SA
__device__ __forceinline__ void split_store4(char* Ah, char* Al, int r, int c, float4 v) {
    uint32_t o = (uint32_t)(r * SA + c) * 2;
    __nv_bfloat162 h01 = __floats2bfloat162_rn(v.x, v.y);
    __nv_bfloat162 h23 = __floats2bfloat162_rn(v.z, v.w);
    float lx = v.x - __bfloat162float(__low2bfloat16(h01));
    float ly = v.y - __bfloat162float(__high2bfloat16(h01));
    float lz = v.z - __bfloat162float(__low2bfloat16(h23));
    float lw = v.w - __bfloat162float(__high2bfloat16(h23));
    *(__nv_bfloat162*)(Ah + o)     = h01;
    *(__nv_bfloat162*)(Ah + o + 4) = h23;
    *(__nv_bfloat162*)(Al + o)     = __floats2bfloat162_rn(lx, ly);
    *(__nv_bfloat162*)(Al + o + 4) = __floats2bfloat162_rn(lz, lw);
}

// ---- the split-bf16 128x128x128 mainloop: acc += A_tile @ B_tile^T ----
// smem layout: Ah @ +0, Al @ +TILEB, Bh @ +2*TILEB, Bl @ +3*TILEB
__device__ __forceinline__ void mma_mainloop(uint32_t base, int lane, int mw, int nw,
                                             float acc[2][8][4]) {
    // A lane address: row = mw*32 + i*16 + (lane&15), col byte = (lane>>4)*16
    uint32_t aB = base + (uint32_t)((mw * 32 + (lane & 15)) * SA) * 2 + ((lane >> 4) * 16);
    // B lane address: row = nw*64 + jp*16 + (lane>>4)*8 + (lane&7), col byte = ((lane>>3)&1)*16
    uint32_t bB = base + 2 * TILEB
                + (uint32_t)((nw * 64 + ((lane >> 4) << 3) + (lane & 7)) * SA) * 2
                + (((lane >> 3) & 1) * 16);
    #pragma unroll
    for (int ks = 0; ks < 8; ks++) {
        const uint32_t ko = ks * 32;
        uint32_t ah[2][4], al[2][4], bh[8][2], bl[8][2];
        LDSM_X4(ah[0], aB + ko);
        LDSM_X4(ah[1], aB + 4352 + ko);           // +16 rows
        LDSM_X4(al[0], aB + TILEB + ko);
        LDSM_X4(al[1], aB + TILEB + 4352 + ko);
        #pragma unroll
        for (int jp = 0; jp < 4; jp++) {
            uint32_t t[4];
            LDSM_X4(t, bB + jp * 4352 + ko);
            bh[2*jp][0] = t[0]; bh[2*jp][1] = t[1];
            bh[2*jp+1][0] = t[2]; bh[2*jp+1][1] = t[3];
            LDSM_X4(t, bB + TILEB + jp * 4352 + ko);
            bl[2*jp][0] = t[0]; bl[2*jp][1] = t[1];
            bl[2*jp+1][0] = t[2]; bl[2*jp+1][1] = t[3];
        }
        #pragma unroll
        for (int j = 0; j < 8; j++)
            #pragma unroll
            for (int i = 0; i < 2; i++) {
                MMA16816(acc[i][j], ah[i], bh[j]);
                MMA16816(acc[i][j], ah[i], bl[j]);
                MMA16816(acc[i][j], al[i], bh[j]);
            }
    }
}

// ===================== setup kernels =====================
__global__ void detect_kernel(const void* __restrict__ ei, int n_elems) {
    if (threadIdx.x == 0 && blockIdx.x == 0) {
        const long long* p = (const long long*)ei;
        int is32 = 0;
        #pragma unroll 1
        for (int i = 0; i < 64; i++) {
            long long v = p[i];
            if (v < 0 || v >= NND) is32 = 1;
        }
        if (n_elems < 2 * NE * 2) is32 = 1;
        g_is32 = is32;
    }
}

__global__ void prep_kernel(const float* __restrict__ Wc, const float* __restrict__ W0,
                            const float* __restrict__ Wt) {
    int i = blockIdx.x * blockDim.x + threadIdx.x;
    if (i < DD * DD) {
        int k = i >> 7, n = i & 127;
        float wc = Wc[i], wt = Wt[i], w0 = W0[i];
        float wt2 = wt + ((k == n) ? 1.0f : 0.0f);
        float wx  = w0 - wt;
        uint32_t o = (uint32_t)(n * SA + k) * 2;   // B[n][k]
        __nv_bfloat16 h;
        h = __float2bfloat16_rn(wc);
        *(__nv_bfloat16*)(gWcH + o)  = h;
        *(__nv_bfloat16*)(gWcL + o)  = __float2bfloat16_rn(wc - __bfloat162float(h));
        h = __float2bfloat16_rn(wt2);
        *(__nv_bfloat16*)(gWt2H + o) = h;
        *(__nv_bfloat16*)(gWt2L + o) = __float2bfloat16_rn(wt2 - __bfloat162float(h));
        h = __float2bfloat16_rn(wx);
        *(__nv_bfloat16*)(gWxH + o)  = h;
        *(__nv_bfloat16*)(gWxL + o)  = __float2bfloat16_rn(wx - __bfloat162float(h));
    }
    if (i < NND) g_cnt[i] = 0;
}

__global__ void convert_hist_kernel(const void* __restrict__ ei) {
    int i = blockIdx.x * blockDim.x + threadIdx.x;
    const int is32 = g_is32;
    if (i < 2 * NE) {
        int v = is32 ? ((const int*)ei)[i] : (int)((const long long*)ei)[i];
        v = min(max(v, 0), NND - 1);
        g_edge[i] = v;
        if (i >= NE) atomicAdd(&g_cnt[v], 1);
    }
}

__global__ __launch_bounds__(1024) void scan_kernel() {
    __shared__ int ssum[1024];
    const int t = threadIdx.x;
    const int CH = (NND + 1023) / 1024;
    int b = t * CH, e = min(b + CH, NND);
    int s = 0;
    for (int i = b; i < e; i++) s += g_cnt[i];
    ssum[t] = s;
    __syncthreads();
    for (int off = 1; off < 1024; off <<= 1) {
        int v = (t >= off) ? ssum[t - off] : 0;
        __syncthreads();
        ssum[t] += v;
        __syncthreads();
    }
    int excl = (t == 0) ? 0 : ssum[t - 1];
    for (int i = b; i < e; i++) {
        g_off[i] = excl;
        g_cur[i] = excl;
        excl += g_cnt[i];
    }
}

__global__ void place_kernel() {
    int e = blockIdx.x * blockDim.x + threadIdx.x;
    if (e < NE) {
        int s = g_edge[e];
        int d = g_edge[NE + e];
        int pos = atomicAdd(&g_cur[d], 1);
        g_srcl[pos] = s;
    }
}

// ===================== GEMM 1: g_xs = (x @ Wc) * dinv =====================
__global__ __launch_bounds__(256) void gemm1_mma(const float* __restrict__ x) {
    extern __shared__ char sm[];
    char* Ah = sm;
    char* Al = sm + TILEB;
    const int tid  = threadIdx.x;
    const int lane = tid & 31, wid = tid >> 5;
    const int mw = wid & 3, nw = wid >> 2;
    const int row0 = blockIdx.x << 7;
    const uint32_t base = smem_u32(sm);

    float4 z4 = make_float4(0.f, 0.f, 0.f, 0.f);
    for (int j = tid; j < 4096; j += 256) {
        int r = j >> 5, c = (j & 31) << 2;
        int gr = row0 + r;
        float4 v = (gr < NND) ? *(const float4*)&x[(size_t)gr * DD + c] : z4;
        split_store4(Ah, Al, r, c, v);
    }
    {
        uint4* dh = (uint4*)(sm + 2 * TILEB);
        uint4* dl = (uint4*)(sm + 3 * TILEB);
        const uint4* sh = (const uint4*)gWcH;
        const uint4* sl = (const uint4*)gWcL;
        for (int j = tid; j < NV4; j += 256) { dh[j] = sh[j]; dl[j] = sl[j]; }
    }
    __syncthreads();

    float acc[2][8][4];
    #pragma unroll
    for (int i = 0; i < 2; i++)
        #pragma unroll
        for (int j = 0; j < 8; j++)
            #pragma unroll
            for (int q = 0; q < 4; q++) acc[i][j][q] = 0.0f;

    mma_mainloop(base, lane, mw, nw, acc);

    // epilogue: scale rows by dinv, store
    #pragma unroll
    for (int i = 0; i < 2; i++) {
        int r1 = row0 + mw * 32 + i * 16 + (lane >> 2);
        int r2 = r1 + 8;
        float s1 = (r1 < NND) ? rsqrtf((float)(g_cnt[r1] + 1)) : 0.0f;
        float s2 = (r2 < NND) ? rsqrtf((float)(g_cnt[r2] + 1)) : 0.0f;
        #pragma unroll
        for (int j = 0; j < 8; j++) {
            int nc = nw * 64 + j * 8 + ((lane & 3) << 1);
            if (r1 < NND) *(float2*)&g_xs[(size_t)r1 * DD + nc] =
                make_float2(acc[i][j][0] * s1, acc[i][j][1] * s1);
            if (r2 < NND) *(float2*)&g_xs[(size_t)r2 * DD + nc] =
                make_float2(acc[i][j][2] * s2, acc[i][j][3] * s2);
        }
    }
}

// ===================== gather =====================
__global__ __launch_bounds__(256) void gather_kernel() {
    const int lane = threadIdx.x & 31;
    int warp = (blockIdx.x * blockDim.x + threadIdx.x) >> 5;
    const int nw = (gridDim.x * blockDim.x) >> 5;
    const int c = lane << 2;

    for (int node = warp; node < NND; node += nw) {
        const int off = g_off[node];
        const int cnt = g_cnt[node];
        float4 a = *(const float4*)&g_xs[(size_t)node * DD + c];
        int j = 0;
        for (; j + 2 <= cnt; j += 2) {
            int s0 = g_srcl[off + j];
            int s1 = g_srcl[off + j + 1];
            float4 v0 = *(const float4*)&g_xs[(size_t)s0 * DD + c];
            float4 v1 = *(const float4*)&g_xs[(size_t)s1 * DD + c];
            a.x += v0.x + v1.x; a.y += v0.y + v1.y;
            a.z += v0.z + v1.z; a.w += v0.w + v1.w;
        }
        if (j < cnt) {
            int s0 = g_srcl[off + j];
            float4 v0 = *(const float4*)&g_xs[(size_t)s0 * DD + c];
            a.x += v0.x; a.y += v0.y; a.z += v0.z; a.w += v0.w;
        }
        *(float4*)&g_acc[(size_t)node * DD + c] = a;
    }
}

// ===================== final: out = h@(I+Wt) + x@(W0-Wt) =====================
__global__ __launch_bounds__(256) void final_mma(const float* __restrict__ x,
                                                 const float* __restrict__ bc,
                                                 float* __restrict__ out) {
    extern __shared__ char sm[];
    char* Ah = sm;
    char* Al = sm + TILEB;
    const int tid  = threadIdx.x;
    const int lane = tid & 31, wid = tid >> 5;
    const int mw = wid & 3, nw = wid >> 2;
    const int row0 = blockIdx.x << 7;
    const uint32_t base = smem_u32(sm);

    float acc[2][8][4];
    #pragma unroll
    for (int i = 0; i < 2; i++)
        #pragma unroll
        for (int j = 0; j < 8; j++)
            #pragma unroll
            for (int q = 0; q < 4; q++) acc[i][j][q] = 0.0f;

    // ---- phase 1: A = h = dinv*g_acc + bc, B = Wt + I ----
    for (int j = tid; j < 4096; j += 256) {
        int r = j >> 5, c = (j & 31) << 2;
        int gr = row0 + r;
        float4 v;
        float4 b4 = *(const float4*)&bc[c];
        if (gr < NND) {
            float s = rsqrtf((float)(g_cnt[gr] + 1));
            float4 a = *(const float4*)&g_acc[(size_t)gr * DD + c];
            v = make_float4(a.x * s + b4.x, a.y * s + b4.y, a.z * s + b4.z, a.w * s + b4.w);
        } else {
            v = make_float4(0.f, 0.f, 0.f, 0.f);
        }
        split_store4(Ah, Al, r, c, v);
    }
    {
        uint4* dh = (uint4*)(sm + 2 * TILEB);
        uint4* dl = (uint4*)(sm + 3 * TILEB);
        const uint4* sh = (const uint4*)gWt2H;
        const uint4* sl = (const uint4*)gWt2L;
        for (int j = tid; j < NV4; j += 256) { dh[j] = sh[j]; dl[j] = sl[j]; }
    }
    __syncthreads();
    mma_mainloop(base, lane, mw, nw, acc);
    __syncthreads();   // everyone done reading smem

    // ---- phase 2: A = x, B = W0 - Wt, accumulate into same regs ----
    float4 z4 = make_float4(0.f, 0.f, 0.f, 0.f);
    for (int j = tid; j < 4096; j += 256) {
        int r = j >> 5, c = (j & 31) << 2;
        int gr = row0 + r;
        float4 v = (gr < NND) ? *(const float4*)&x[(size_t)gr * DD + c] : z4;
        split_store4(Ah, Al, r, c, v);
    }
    {
        uint4* dh = (uint4*)(sm + 2 * TILEB);
        uint4* dl = (uint4*)(sm + 3 * TILEB);
        const uint4* sh = (const uint4*)gWxH;
        const uint4* sl = (const uint4*)gWxL;
        for (int j = tid; j < NV4; j += 256) { dh[j] = sh[j]; dl[j] = sl[j]; }
    }
    __syncthreads();
    mma_mainloop(base, lane, mw, nw, acc);

    // epilogue
    #pragma unroll
    for (int i = 0; i < 2; i++) {
        int r1 = row0 + mw * 32 + i * 16 + (lane >> 2);
        int r2 = r1 + 8;
        #pragma unroll
        for (int j = 0; j < 8; j++) {
            int nc = nw * 64 + j * 8 + ((lane & 3) << 1);
            if (r1 < NND) *(float2*)&out[(size_t)r1 * DD + nc] =
                make_float2(acc[i][j][0], acc[i][j][1]);
            if (r2 < NND) *(float2*)&out[(size_t)r2 * DD + nc] =
                make_float2(acc[i][j][2], acc[i][j][3]);
        }
    }
}

// ===================== launch =====================
extern "C" void kernel_launch(void* const* d_in, const int* in_sizes, int n_in,
                              void* d_out, int out_size) {
    const float* x  = (const float*)d_in[0];
    const void*  ei = d_in[1];
    const float* Wc = (const float*)d_in[2];
    const float* bc = (const float*)d_in[3];
    const float* W0 = (const float*)d_in[4];
    const float* Wt = (const float*)d_in[5];
    float* out = (float*)d_out;

    const int gemm_blocks = (NND + 127) / 128;   // 391
    const int DSM = 4 * TILEB;                   // 139264 B

    cudaFuncSetAttribute(gemm1_mma, cudaFuncAttributeMaxDynamicSharedMemorySize, DSM);
    cudaFuncSetAttribute(final_mma, cudaFuncAttributeMaxDynamicSharedMemorySize, DSM);

    detect_kernel<<<1, 32>>>(ei, in_sizes[1]);
    prep_kernel<<<(NND + 255) / 256, 256>>>(Wc, W0, Wt);
    convert_hist_kernel<<<(2 * NE + 255) / 256, 256>>>(ei);
    scan_kernel<<<1, 1024>>>();
    place_kernel<<<(NE + 255) / 256, 256>>>();
    gemm1_mma<<<gemm_blocks, 256, DSM>>>(x);
    gather_kernel<<<2048, 256>>>();
    final_mma<<<gemm_blocks, 256, DSM>>>(x, bc, out);
}

// round 9
// speedup vs baseline: 2.2621x; 1.4270x over previous
#include <cuda_runtime.h>
#include <cuda_bf16.h>
#include <cstdint>

#define NND 50000
#define NE  800000
#define DD  128

#define SA      136                 // smem row stride in bf16 elems
#define TILEB   34816               // 128*136*2 bytes per bf16 tile buffer
#define NV4     2176                // TILEB/16

// ---- device scratch ----
__device__ int g_is32;
__device__ int g_total;
__device__ __align__(16) int   g_edge[2 * NE];
__device__ __align__(16) int   g_cnt[NND];
__device__ __align__(16) int   g_off[NND];
__device__ __align__(16) int   g_cur[NND];
__device__ __align__(16) int   g_srcl[NE];
__device__ __align__(16) float g_xs[(size_t)NND * DD];
__device__ __align__(16) float g_acc[(size_t)NND * DD];
// weights pre-transposed to B[n][k] = W[k][n], bf16 hi/lo split, stride SA
__device__ __align__(16) unsigned char gWcH[TILEB],  gWcL[TILEB];
__device__ __align__(16) unsigned char gWt2H[TILEB], gWt2L[TILEB];
__device__ __align__(16) unsigned char gWxH[TILEB],  gWxL[TILEB];

// ===================== PTX wrappers (all baseline, no 'a' features) =========
__device__ __forceinline__ uint32_t smem_u32(const void* p) {
    uint32_t a;
    asm("{ .reg .u64 t; cvta.to.shared.u64 t, %1; cvt.u32.u64 %0, t; }" : "=r"(a) : "l"(p));
    return a;
}
#define LDSM_X4(r, a)                                                           \
    asm volatile("ldmatrix.sync.aligned.m8n8.x4.shared.b16 {%0,%1,%2,%3}, [%4];"\
        : "=r"((r)[0]), "=r"((r)[1]), "=r"((r)[2]), "=r"((r)[3]) : "r"(a))
#define MMA16816(d, a, b)                                                       \
    asm volatile("mma.sync.aligned.m16n8k16.row.col.f32.bf16.bf16.f32 "         \
        "{%0,%1,%2,%3}, {%4,%5,%6,%7}, {%8,%9}, {%0,%1,%2,%3};"                 \
        : "+f"((d)[0]), "+f"((d)[1]), "+f"((d)[2]), "+f"((d)[3])                \
        : "r"((a)[0]), "r"((a)[1]), "r"((a)[2]), "r"((a)[3]),                   \
          "r"((b)[0]), "r"((b)[1]))

// split fp32x4 -> bf16 hi/lo, store 4 elems at (r, c), c % 4 == 0, stride SA
__device__ __forceinline__ void split_store4(char* Ah, char* Al, int r, int c, float4 v) {
    uint32_t o = (uint32_t)(r * SA + c) * 2;
    __nv_bfloat162 h01 = __floats2bfloat162_rn(v.x, v.y);
    __nv_bfloat162 h23 = __floats2bfloat162_rn(v.z, v.w);
    float lx = v.x - __bfloat162float(__low2bfloat16(h01));
    float ly = v.y - __bfloat162float(__high2bfloat16(h01));
    float lz = v.z - __bfloat162float(__low2bfloat16(h23));
    float lw = v.w - __bfloat162float(__high2bfloat16(h23));
    *(__nv_bfloat162*)(Ah + o)     = h01;
    *(__nv_bfloat162*)(Ah + o + 4) = h23;
    *(__nv_bfloat162*)(Al + o)     = __floats2bfloat162_rn(lx, ly);
    *(__nv_bfloat162*)(Al + o + 4) = __floats2bfloat162_rn(lz, lw);
}

// ---- the split-bf16 128x128x128 mainloop: acc += A_tile @ B_tile^T ----
// smem layout: Ah @ +0, Al @ +TILEB, Bh @ +2*TILEB, Bl @ +3*TILEB
__device__ __forceinline__ void mma_mainloop(uint32_t base, int lane, int mw, int nw,
                                             float acc[2][8][4]) {
    uint32_t aB = base + (uint32_t)((mw * 32 + (lane & 15)) * SA) * 2 + ((lane >> 4) * 16);
    uint32_t bB = base + 2 * TILEB
                + (uint32_t)((nw * 64 + ((lane >> 4) << 3) + (lane & 7)) * SA) * 2
                + (((lane >> 3) & 1) * 16);
    #pragma unroll
    for (int ks = 0; ks < 8; ks++) {
        const uint32_t ko = ks * 32;
        uint32_t ah[2][4], al[2][4], bh[8][2], bl[8][2];
        LDSM_X4(ah[0], aB + ko);
        LDSM_X4(ah[1], aB + 4352 + ko);           // +16 rows
        LDSM_X4(al[0], aB + TILEB + ko);
        LDSM_X4(al[1], aB + TILEB + 4352 + ko);
        #pragma unroll
        for (int jp = 0; jp < 4; jp++) {
            uint32_t t[4];
            LDSM_X4(t, bB + jp * 4352 + ko);
            bh[2*jp][0] = t[0]; bh[2*jp][1] = t[1];
            bh[2*jp+1][0] = t[2]; bh[2*jp+1][1] = t[3];
            LDSM_X4(t, bB + TILEB + jp * 4352 + ko);
            bl[2*jp][0] = t[0]; bl[2*jp][1] = t[1];
            bl[2*jp+1][0] = t[2]; bl[2*jp+1][1] = t[3];
        }
        #pragma unroll
        for (int j = 0; j < 8; j++)
            #pragma unroll
            for (int i = 0; i < 2; i++) {
                MMA16816(acc[i][j], ah[i], bh[j]);
                MMA16816(acc[i][j], ah[i], bl[j]);
                MMA16816(acc[i][j], al[i], bh[j]);
            }
    }
}

// ===================== setup kernels =====================
__global__ void detect_kernel(const void* __restrict__ ei, int n_elems) {
    if (threadIdx.x == 0 && blockIdx.x == 0) {
        const long long* p = (const long long*)ei;
        int is32 = 0;
        #pragma unroll 1
        for (int i = 0; i < 64; i++) {
            long long v = p[i];
            if (v < 0 || v >= NND) is32 = 1;
        }
        if (n_elems < 2 * NE * 2) is32 = 1;
        g_is32 = is32;
        g_total = 0;
    }
}

__global__ void prep_kernel(const float* __restrict__ Wc, const float* __restrict__ W0,
                            const float* __restrict__ Wt) {
    int i = blockIdx.x * blockDim.x + threadIdx.x;
    if (i < DD * DD) {
        int k = i >> 7, n = i & 127;
        float wc = Wc[i], wt = Wt[i], w0 = W0[i];
        float wt2 = wt + ((k == n) ? 1.0f : 0.0f);
        float wx  = w0 - wt;
        uint32_t o = (uint32_t)(n * SA + k) * 2;   // B[n][k]
        __nv_bfloat16 h;
        h = __float2bfloat16_rn(wc);
        *(__nv_bfloat16*)(gWcH + o)  = h;
        *(__nv_bfloat16*)(gWcL + o)  = __float2bfloat16_rn(wc - __bfloat162float(h));
        h = __float2bfloat16_rn(wt2);
        *(__nv_bfloat16*)(gWt2H + o) = h;
        *(__nv_bfloat16*)(gWt2L + o) = __float2bfloat16_rn(wt2 - __bfloat162float(h));
        h = __float2bfloat16_rn(wx);
        *(__nv_bfloat16*)(gWxH + o)  = h;
        *(__nv_bfloat16*)(gWxL + o)  = __float2bfloat16_rn(wx - __bfloat162float(h));
    }
    if (i < NND) g_cnt[i] = 0;
}

__global__ void convert_hist_kernel(const void* __restrict__ ei) {
    int i = blockIdx.x * blockDim.x + threadIdx.x;
    const int is32 = g_is32;
    if (i < 2 * NE) {
        int v = is32 ? ((const int*)ei)[i] : (int)((const long long*)ei)[i];
        v = min(max(v, 0), NND - 1);
        g_edge[i] = v;
        if (i >= NE) atomicAdd(&g_cnt[v], 1);
    }
}

// parallel CSR offset allocation (order-free: ranges only need to be disjoint)
__global__ __launch_bounds__(256) void alloc_kernel() {
    __shared__ int wsum[8];
    __shared__ int blockBase;
    const int tid = threadIdx.x;
    const int lane = tid & 31, w = tid >> 5;
    int i = blockIdx.x * 256 + tid;
    int cnt = (i < NND) ? g_cnt[i] : 0;

    // warp inclusive prefix sum
    int pre = cnt;
    #pragma unroll
    for (int o = 1; o < 32; o <<= 1) {
        int v = __shfl_up_sync(0xFFFFFFFFu, pre, o);
        if (lane >= o) pre += v;
    }
    if (lane == 31) wsum[w] = pre;
    __syncthreads();
    if (tid == 0) {
        int t = 0;
        #pragma unroll
        for (int k = 0; k < 8; k++) { int v = wsum[k]; wsum[k] = t; t += v; }
        blockBase = atomicAdd(&g_total, t);
    }
    __syncthreads();
    if (i < NND) {
        int off = blockBase + wsum[w] + pre - cnt;   // exclusive within block
        g_off[i] = off;
        g_cur[i] = off;
    }
}

__global__ void place_kernel() {
    int e = blockIdx.x * blockDim.x + threadIdx.x;
    if (e < NE) {
        int s = g_edge[e];
        int d = g_edge[NE + e];
        int pos = atomicAdd(&g_cur[d], 1);
        g_srcl[pos] = s;
    }
}

// ===================== GEMM 1: g_xs = (x @ Wc) * dinv =====================
__global__ __launch_bounds__(256) void gemm1_mma(const float* __restrict__ x) {
    extern __shared__ char sm[];
    char* Ah = sm;
    char* Al = sm + TILEB;
    const int tid  = threadIdx.x;
    const int lane = tid & 31, wid = tid >> 5;
    const int mw = wid & 3, nw = wid >> 2;
    const int row0 = blockIdx.x << 7;
    const uint32_t base = smem_u32(sm);

    float4 z4 = make_float4(0.f, 0.f, 0.f, 0.f);
    for (int j = tid; j < 4096; j += 256) {
        int r = j >> 5, c = (j & 31) << 2;
        int gr = row0 + r;
        float4 v = (gr < NND) ? *(const float4*)&x[(size_t)gr * DD + c] : z4;
        split_store4(Ah, Al, r, c, v);
    }
    {
        uint4* dh = (uint4*)(sm + 2 * TILEB);
        uint4* dl = (uint4*)(sm + 3 * TILEB);
        const uint4* sh = (const uint4*)gWcH;
        const uint4* sl = (const uint4*)gWcL;
        for (int j = tid; j < NV4; j += 256) { dh[j] = sh[j]; dl[j] = sl[j]; }
    }
    __syncthreads();

    float acc[2][8][4];
    #pragma unroll
    for (int i = 0; i < 2; i++)
        #pragma unroll
        for (int j = 0; j < 8; j++)
            #pragma unroll
            for (int q = 0; q < 4; q++) acc[i][j][q] = 0.0f;

    mma_mainloop(base, lane, mw, nw, acc);

    // epilogue: scale rows by dinv, store
    #pragma unroll
    for (int i = 0; i < 2; i++) {
        int r1 = row0 + mw * 32 + i * 16 + (lane >> 2);
        int r2 = r1 + 8;
        float s1 = (r1 < NND) ? rsqrtf((float)(g_cnt[r1] + 1)) : 0.0f;
        float s2 = (r2 < NND) ? rsqrtf((float)(g_cnt[r2] + 1)) : 0.0f;
        #pragma unroll
        for (int j = 0; j < 8; j++) {
            int nc = nw * 64 + j * 8 + ((lane & 3) << 1);
            if (r1 < NND) *(float2*)&g_xs[(size_t)r1 * DD + nc] =
                make_float2(acc[i][j][0] * s1, acc[i][j][1] * s1);
            if (r2 < NND) *(float2*)&g_xs[(size_t)r2 * DD + nc] =
                make_float2(acc[i][j][2] * s2, acc[i][j][3] * s2);
        }
    }
}

// ===================== gather =====================
__global__ __launch_bounds__(256) void gather_kernel() {
    const int lane = threadIdx.x & 31;
    int warp = (blockIdx.x * blockDim.x + threadIdx.x) >> 5;
    const int nw = (gridDim.x * blockDim.x) >> 5;
    const int c = lane << 2;

    for (int node = warp; node < NND; node += nw) {
        const int off = g_off[node];
        const int cnt = g_cnt[node];
        float4 a = *(const float4*)&g_xs[(size_t)node * DD + c];
        int j = 0;
        for (; j + 2 <= cnt; j += 2) {
            int s0 = g_srcl[off + j];
            int s1 = g_srcl[off + j + 1];
            float4 v0 = *(const float4*)&g_xs[(size_t)s0 * DD + c];
            float4 v1 = *(const float4*)&g_xs[(size_t)s1 * DD + c];
            a.x += v0.x + v1.x; a.y += v0.y + v1.y;
            a.z += v0.z + v1.z; a.w += v0.w + v1.w;
        }
        if (j < cnt) {
            int s0 = g_srcl[off + j];
            float4 v0 = *(const float4*)&g_xs[(size_t)s0 * DD + c];
            a.x += v0.x; a.y += v0.y; a.z += v0.z; a.w += v0.w;
        }
        *(float4*)&g_acc[(size_t)node * DD + c] = a;
    }
}

// ===================== final: out = h@(I+Wt) + x@(W0-Wt) =====================
__global__ __launch_bounds__(256) void final_mma(const float* __restrict__ x,
                                                 const float* __restrict__ bc,
                                                 float* __restrict__ out) {
    extern __shared__ char sm[];
    char* Ah = sm;
    char* Al = sm + TILEB;
    const int tid  = threadIdx.x;
    const int lane = tid & 31, wid = tid >> 5;
    const int mw = wid & 3, nw = wid >> 2;
    const int row0 = blockIdx.x << 7;
    const uint32_t base = smem_u32(sm);

    float acc[2][8][4];
    #pragma unroll
    for (int i = 0; i < 2; i++)
        #pragma unroll
        for (int j = 0; j < 8; j++)
            #pragma unroll
            for (int q = 0; q < 4; q++) acc[i][j][q] = 0.0f;

    // ---- phase 1: A = h = dinv*g_acc + bc, B = Wt + I ----
    for (int j = tid; j < 4096; j += 256) {
        int r = j >> 5, c = (j & 31) << 2;
        int gr = row0 + r;
        float4 v;
        float4 b4 = *(const float4*)&bc[c];
        if (gr < NND) {
            float s = rsqrtf((float)(g_cnt[gr] + 1));
            float4 a = *(const float4*)&g_acc[(size_t)gr * DD + c];
            v = make_float4(a.x * s + b4.x, a.y * s + b4.y, a.z * s + b4.z, a.w * s + b4.w);
        } else {
            v = make_float4(0.f, 0.f, 0.f, 0.f);
        }
        split_store4(Ah, Al, r, c, v);
    }
    {
        uint4* dh = (uint4*)(sm + 2 * TILEB);
        uint4* dl = (uint4*)(sm + 3 * TILEB);
        const uint4* sh = (const uint4*)gWt2H;
        const uint4* sl = (const uint4*)gWt2L;
        for (int j = tid; j < NV4; j += 256) { dh[j] = sh[j]; dl[j] = sl[j]; }
    }
    __syncthreads();
    mma_mainloop(base, lane, mw, nw, acc);
    __syncthreads();   // everyone done reading smem

    // ---- phase 2: A = x, B = W0 - Wt, accumulate into same regs ----
    float4 z4 = make_float4(0.f, 0.f, 0.f, 0.f);
    for (int j = tid; j < 4096; j += 256) {
        int r = j >> 5, c = (j & 31) << 2;
        int gr = row0 + r;
        float4 v = (gr < NND) ? *(const float4*)&x[(size_t)gr * DD + c] : z4;
        split_store4(Ah, Al, r, c, v);
    }
    {
        uint4* dh = (uint4*)(sm + 2 * TILEB);
        uint4* dl = (uint4*)(sm + 3 * TILEB);
        const uint4* sh = (const uint4*)gWxH;
        const uint4* sl = (const uint4*)gWxL;
        for (int j = tid; j < NV4; j += 256) { dh[j] = sh[j]; dl[j] = sl[j]; }
    }
    __syncthreads();
    mma_mainloop(base, lane, mw, nw, acc);

    // epilogue
    #pragma unroll
    for (int i = 0; i < 2; i++) {
        int r1 = row0 + mw * 32 + i * 16 + (lane >> 2);
        int r2 = r1 + 8;
        #pragma unroll
        for (int j = 0; j < 8; j++) {
            int nc = nw * 64 + j * 8 + ((lane & 3) << 1);
            if (r1 < NND) *(float2*)&out[(size_t)r1 * DD + nc] =
                make_float2(acc[i][j][0], acc[i][j][1]);
            if (r2 < NND) *(float2*)&out[(size_t)r2 * DD + nc] =
                make_float2(acc[i][j][2], acc[i][j][3]);
        }
    }
}

// ===================== launch =====================
extern "C" void kernel_launch(void* const* d_in, const int* in_sizes, int n_in,
                              void* d_out, int out_size) {
    const float* x  = (const float*)d_in[0];
    const void*  ei = d_in[1];
    const float* Wc = (const float*)d_in[2];
    const float* bc = (const float*)d_in[3];
    const float* W0 = (const float*)d_in[4];
    const float* Wt = (const float*)d_in[5];
    float* out = (float*)d_out;

    const int gemm_blocks = (NND + 127) / 128;   // 391
    const int DSM = 4 * TILEB;                   // 139264 B

    cudaFuncSetAttribute(gemm1_mma, cudaFuncAttributeMaxDynamicSharedMemorySize, DSM);
    cudaFuncSetAttribute(final_mma, cudaFuncAttributeMaxDynamicSharedMemorySize, DSM);

    detect_kernel<<<1, 32>>>(ei, in_sizes[1]);
    prep_kernel<<<(NND + 255) / 256, 256>>>(Wc, W0, Wt);
    convert_hist_kernel<<<(2 * NE + 255) / 256, 256>>>(ei);
    alloc_kernel<<<(NND + 255) / 256, 256>>>();
    place_kernel<<<(NE + 255) / 256, 256>>>();
    gemm1_mma<<<gemm_blocks, 256, DSM>>>(x);
    gather_kernel<<<2048, 256>>>();
    final_mma<<<gemm_blocks, 256, DSM>>>(x, bc, out);
}

// round 10
// speedup vs baseline: 2.3153x; 1.0236x over previous
#include <cuda_runtime.h>
#include <cuda_bf16.h>
#include <cstdint>

#define NND 50000
#define NE  800000
#define DD  128

#define SA      136                 // smem row stride in bf16 elems
#define TILEB   34816               // 128*136*2 bytes per bf16 tile buffer
#define NV4     2176                // TILEB/16

// ---- device scratch ----
__device__ int g_is32;
__device__ int g_total;
__device__ __align__(16) int   g_cnt[NND];
__device__ __align__(16) int   g_off[NND];
__device__ __align__(16) int   g_cur[NND];
__device__ __align__(16) float g_dinv[NND];
__device__ __align__(16) int   g_srcl[NE];
__device__ __align__(16) float g_xs[(size_t)NND * DD];   // xw = x @ Wc (unscaled)
__device__ __align__(16) float g_acc[(size_t)NND * DD];  // S[d] = sum dinv[s]*xw[s]
// weights pre-transposed to B[n][k] = W[k][n], bf16 hi/lo split, stride SA
__device__ __align__(16) unsigned char gWcH[TILEB],  gWcL[TILEB];
__device__ __align__(16) unsigned char gWt2H[TILEB], gWt2L[TILEB];
__device__ __align__(16) unsigned char gWxH[TILEB],  gWxL[TILEB];

// ===================== PTX wrappers =====================
__device__ __forceinline__ uint32_t smem_u32(const void* p) {
    uint32_t a;
    asm("{ .reg .u64 t; cvta.to.shared.u64 t, %1; cvt.u32.u64 %0, t; }" : "=r"(a) : "l"(p));
    return a;
}
#define LDSM_X4(r, a)                                                           \
    asm volatile("ldmatrix.sync.aligned.m8n8.x4.shared.b16 {%0,%1,%2,%3}, [%4];"\
        : "=r"((r)[0]), "=r"((r)[1]), "=r"((r)[2]), "=r"((r)[3]) : "r"(a))
#define MMA16816(d, a, b)                                                       \
    asm volatile("mma.sync.aligned.m16n8k16.row.col.f32.bf16.bf16.f32 "         \
        "{%0,%1,%2,%3}, {%4,%5,%6,%7}, {%8,%9}, {%0,%1,%2,%3};"                 \
        : "+f"((d)[0]), "+f"((d)[1]), "+f"((d)[2]), "+f"((d)[3])                \
        : "r"((a)[0]), "r"((a)[1]), "r"((a)[2]), "r"((a)[3]),                   \
          "r"((b)[0]), "r"((b)[1]))

__device__ __forceinline__ void split_store4(char* Ah, char* Al, int r, int c, float4 v) {
    uint32_t o = (uint32_t)(r * SA + c) * 2;
    __nv_bfloat162 h01 = __floats2bfloat162_rn(v.x, v.y);
    __nv_bfloat162 h23 = __floats2bfloat162_rn(v.z, v.w);
    float lx = v.x - __bfloat162float(__low2bfloat16(h01));
    float ly = v.y - __bfloat162float(__high2bfloat16(h01));
    float lz = v.z - __bfloat162float(__low2bfloat16(h23));
    float lw = v.w - __bfloat162float(__high2bfloat16(h23));
    *(__nv_bfloat162*)(Ah + o)     = h01;
    *(__nv_bfloat162*)(Ah + o + 4) = h23;
    *(__nv_bfloat162*)(Al + o)     = __floats2bfloat162_rn(lx, ly);
    *(__nv_bfloat162*)(Al + o + 4) = __floats2bfloat162_rn(lz, lw);
}

// ---- split-bf16 128x128x128 mainloop: acc += A_tile @ B_tile^T ----
__device__ __forceinline__ void mma_mainloop(uint32_t base, int lane, int mw, int nw,
                                             float acc[2][8][4]) {
    uint32_t aB = base + (uint32_t)((mw * 32 + (lane & 15)) * SA) * 2 + ((lane >> 4) * 16);
    uint32_t bB = base + 2 * TILEB
                + (uint32_t)((nw * 64 + ((lane >> 4) << 3) + (lane & 7)) * SA) * 2
                + (((lane >> 3) & 1) * 16);
    #pragma unroll
    for (int ks = 0; ks < 8; ks++) {
        const uint32_t ko = ks * 32;
        uint32_t ah[2][4], al[2][4], bh[8][2], bl[8][2];
        LDSM_X4(ah[0], aB + ko);
        LDSM_X4(ah[1], aB + 4352 + ko);
        LDSM_X4(al[0], aB + TILEB + ko);
        LDSM_X4(al[1], aB + TILEB + 4352 + ko);
        #pragma unroll
        for (int jp = 0; jp < 4; jp++) {
            uint32_t t[4];
            LDSM_X4(t, bB + jp * 4352 + ko);
            bh[2*jp][0] = t[0]; bh[2*jp][1] = t[1];
            bh[2*jp+1][0] = t[2]; bh[2*jp+1][1] = t[3];
            LDSM_X4(t, bB + TILEB + jp * 4352 + ko);
            bl[2*jp][0] = t[0]; bl[2*jp][1] = t[1];
            bl[2*jp+1][0] = t[2]; bl[2*jp+1][1] = t[3];
        }
        #pragma unroll
        for (int j = 0; j < 8; j++)
            #pragma unroll
            for (int i = 0; i < 2; i++) {
                MMA16816(acc[i][j], ah[i], bh[j]);
                MMA16816(acc[i][j], ah[i], bl[j]);
                MMA16816(acc[i][j], al[i], bh[j]);
            }
    }
}

// ===================== setup kernels =====================
// detect dtype + zero histogram (block 0 thread 0 detects; all threads zero)
__global__ void detect_kernel(const void* __restrict__ ei, int n_elems) {
    int i = blockIdx.x * blockDim.x + threadIdx.x;
    if (i < NND) g_cnt[i] = 0;
    if (i == 0) {
        const long long* p = (const long long*)ei;
        int is32 = 0;
        #pragma unroll 1
        for (int k = 0; k < 64; k++) {
            long long v = p[k];
            if (v < 0 || v >= NND) is32 = 1;
        }
        if (n_elems < 2 * NE * 2) is32 = 1;
        g_is32 = is32;
        g_total = 0;
    }
}

__global__ void prep_kernel(const float* __restrict__ Wc, const float* __restrict__ W0,
                            const float* __restrict__ Wt) {
    int i = blockIdx.x * blockDim.x + threadIdx.x;
    if (i < DD * DD) {
        int k = i >> 7, n = i & 127;
        float wc = Wc[i], wt = Wt[i], w0 = W0[i];
        float wt2 = wt + ((k == n) ? 1.0f : 0.0f);
        float wx  = w0 - wt;
        uint32_t o = (uint32_t)(n * SA + k) * 2;   // B[n][k]
        __nv_bfloat16 h;
        h = __float2bfloat16_rn(wc);
        *(__nv_bfloat16*)(gWcH + o)  = h;
        *(__nv_bfloat16*)(gWcL + o)  = __float2bfloat16_rn(wc - __bfloat162float(h));
        h = __float2bfloat16_rn(wt2);
        *(__nv_bfloat16*)(gWt2H + o) = h;
        *(__nv_bfloat16*)(gWt2L + o) = __float2bfloat16_rn(wt2 - __bfloat162float(h));
        h = __float2bfloat16_rn(wx);
        *(__nv_bfloat16*)(gWxH + o)  = h;
        *(__nv_bfloat16*)(gWxL + o)  = __float2bfloat16_rn(wx - __bfloat162float(h));
    }
}

__device__ __forceinline__ int load_idx(const void* ei, int i, int is32) {
    int v = is32 ? ((const int*)ei)[i] : (int)((const long long*)ei)[i];
    return min(max(v, 0), NND - 1);
}

// dst histogram straight from edge_index
__global__ void hist_kernel(const void* __restrict__ ei) {
    int e = blockIdx.x * blockDim.x + threadIdx.x;
    if (e < NE) atomicAdd(&g_cnt[load_idx(ei, NE + e, g_is32)], 1);
}

// parallel CSR offset allocation + dinv precompute
__global__ __launch_bounds__(256) void alloc_kernel() {
    __shared__ int wsum[8];
    __shared__ int blockBase;
    const int tid = threadIdx.x;
    const int lane = tid & 31, w = tid >> 5;
    int i = blockIdx.x * 256 + tid;
    int cnt = (i < NND) ? g_cnt[i] : 0;

    int pre = cnt;
    #pragma unroll
    for (int o = 1; o < 32; o <<= 1) {
        int v = __shfl_up_sync(0xFFFFFFFFu, pre, o);
        if (lane >= o) pre += v;
    }
    if (lane == 31) wsum[w] = pre;
    __syncthreads();
    if (tid == 0) {
        int t = 0;
        #pragma unroll
        for (int k = 0; k < 8; k++) { int v = wsum[k]; wsum[k] = t; t += v; }
        blockBase = atomicAdd(&g_total, t);
    }
    __syncthreads();
    if (i < NND) {
        int off = blockBase + wsum[w] + pre - cnt;
        g_off[i] = off;
        g_cur[i] = off;
        g_dinv[i] = rsqrtf((float)(cnt + 1));
    }
}

__global__ void place_kernel(const void* __restrict__ ei) {
    int e = blockIdx.x * blockDim.x + threadIdx.x;
    if (e < NE) {
        const int is32 = g_is32;
        int s = load_idx(ei, e, is32);
        int d = load_idx(ei, NE + e, is32);
        int pos = atomicAdd(&g_cur[d], 1);
        g_srcl[pos] = s;
    }
}

// ===================== GEMM 1: g_xs = x @ Wc (unscaled) =====================
__global__ __launch_bounds__(256) void gemm1_mma(const float* __restrict__ x) {
    extern __shared__ char sm[];
    char* Ah = sm;
    char* Al = sm + TILEB;
    const int tid  = threadIdx.x;
    const int lane = tid & 31, wid = tid >> 5;
    const int mw = wid & 3, nw = wid >> 2;
    const int row0 = blockIdx.x << 7;
    const uint32_t base = smem_u32(sm);

    float4 z4 = make_float4(0.f, 0.f, 0.f, 0.f);
    for (int j = tid; j < 4096; j += 256) {
        int r = j >> 5, c = (j & 31) << 2;
        int gr = row0 + r;
        float4 v = (gr < NND) ? *(const float4*)&x[(size_t)gr * DD + c] : z4;
        split_store4(Ah, Al, r, c, v);
    }
    {
        uint4* dh = (uint4*)(sm + 2 * TILEB);
        uint4* dl = (uint4*)(sm + 3 * TILEB);
        const uint4* sh = (const uint4*)gWcH;
        const uint4* sl = (const uint4*)gWcL;
        for (int j = tid; j < NV4; j += 256) { dh[j] = sh[j]; dl[j] = sl[j]; }
    }
    __syncthreads();

    float acc[2][8][4];
    #pragma unroll
    for (int i = 0; i < 2; i++)
        #pragma unroll
        for (int j = 0; j < 8; j++)
            #pragma unroll
            for (int q = 0; q < 4; q++) acc[i][j][q] = 0.0f;

    mma_mainloop(base, lane, mw, nw, acc);

    #pragma unroll
    for (int i = 0; i < 2; i++) {
        int r1 = row0 + mw * 32 + i * 16 + (lane >> 2);
        int r2 = r1 + 8;
        #pragma unroll
        for (int j = 0; j < 8; j++) {
            int nc = nw * 64 + j * 8 + ((lane & 3) << 1);
            if (r1 < NND) *(float2*)&g_xs[(size_t)r1 * DD + nc] =
                make_float2(acc[i][j][0], acc[i][j][1]);
            if (r2 < NND) *(float2*)&g_xs[(size_t)r2 * DD + nc] =
                make_float2(acc[i][j][2], acc[i][j][3]);
        }
    }
}

// ===================== gather: S[d] = sum_{s in N(d) ∪ {d}} dinv[s]*xw[s] ====
__global__ __launch_bounds__(256) void gather_kernel() {
    const int lane = threadIdx.x & 31;
    int warp = (blockIdx.x * blockDim.x + threadIdx.x) >> 5;
    const int nw = (gridDim.x * blockDim.x) >> 5;
    const int c = lane << 2;

    for (int node = warp; node < NND; node += nw) {
        const int off = g_off[node];
        const int cnt = g_cnt[node];
        const float dn = g_dinv[node];
        float4 a = *(const float4*)&g_xs[(size_t)node * DD + c];
        a.x *= dn; a.y *= dn; a.z *= dn; a.w *= dn;
        int j = 0;
        for (; j + 2 <= cnt; j += 2) {
            int s0 = g_srcl[off + j];
            int s1 = g_srcl[off + j + 1];
            float d0 = g_dinv[s0], d1 = g_dinv[s1];
            float4 v0 = *(const float4*)&g_xs[(size_t)s0 * DD + c];
            float4 v1 = *(const float4*)&g_xs[(size_t)s1 * DD + c];
            a.x += d0 * v0.x + d1 * v1.x;
            a.y += d0 * v0.y + d1 * v1.y;
            a.z += d0 * v0.z + d1 * v1.z;
            a.w += d0 * v0.w + d1 * v1.w;
        }
        if (j < cnt) {
            int s0 = g_srcl[off + j];
            float d0 = g_dinv[s0];
            float4 v0 = *(const float4*)&g_xs[(size_t)s0 * DD + c];
            a.x += d0 * v0.x; a.y += d0 * v0.y;
            a.z += d0 * v0.z; a.w += d0 * v0.w;
        }
        *(float4*)&g_acc[(size_t)node * DD + c] = a;
    }
}

// ===================== final: out = h@(I+Wt) + x@(W0-Wt) =====================
__global__ __launch_bounds__(256) void final_mma(const float* __restrict__ x,
                                                 const float* __restrict__ bc,
                                                 float* __restrict__ out) {
    extern __shared__ char sm[];
    char* Ah = sm;
    char* Al = sm + TILEB;
    const int tid  = threadIdx.x;
    const int lane = tid & 31, wid = tid >> 5;
    const int mw = wid & 3, nw = wid >> 2;
    const int row0 = blockIdx.x << 7;
    const uint32_t base = smem_u32(sm);

    float acc[2][8][4];
    #pragma unroll
    for (int i = 0; i < 2; i++)
        #pragma unroll
        for (int j = 0; j < 8; j++)
            #pragma unroll
            for (int q = 0; q < 4; q++) acc[i][j][q] = 0.0f;

    // ---- phase 1: A = h = dinv*S + bc, B = Wt + I ----
    for (int j = tid; j < 4096; j += 256) {
        int r = j >> 5, c = (j & 31) << 2;
        int gr = row0 + r;
        float4 v;
        float4 b4 = *(const float4*)&bc[c];
        if (gr < NND) {
            float s = g_dinv[gr];
            float4 a = *(const float4*)&g_acc[(size_t)gr * DD + c];
            v = make_float4(a.x * s + b4.x, a.y * s + b4.y, a.z * s + b4.z, a.w * s + b4.w);
        } else {
            v = make_float4(0.f, 0.f, 0.f, 0.f);
        }
        split_store4(Ah, Al, r, c, v);
    }
    {
        uint4* dh = (uint4*)(sm + 2 * TILEB);
        uint4* dl = (uint4*)(sm + 3 * TILEB);
        const uint4* sh = (const uint4*)gWt2H;
        const uint4* sl = (const uint4*)gWt2L;
        for (int j = tid; j < NV4; j += 256) { dh[j] = sh[j]; dl[j] = sl[j]; }
    }
    __syncthreads();
    mma_mainloop(base, lane, mw, nw, acc);
    __syncthreads();

    // ---- phase 2: A = x, B = W0 - Wt ----
    float4 z4 = make_float4(0.f, 0.f, 0.f, 0.f);
    for (int j = tid; j < 4096; j += 256) {
        int r = j >> 5, c = (j & 31) << 2;
        int gr = row0 + r;
        float4 v = (gr < NND) ? *(const float4*)&x[(size_t)gr * DD + c] : z4;
        split_store4(Ah, Al, r, c, v);
    }
    {
        uint4* dh = (uint4*)(sm + 2 * TILEB);
        uint4* dl = (uint4*)(sm + 3 * TILEB);
        const uint4* sh = (const uint4*)gWxH;
        const uint4* sl = (const uint4*)gWxL;
        for (int j = tid; j < NV4; j += 256) { dh[j] = sh[j]; dl[j] = sl[j]; }
    }
    __syncthreads();
    mma_mainloop(base, lane, mw, nw, acc);

    #pragma unroll
    for (int i = 0; i < 2; i++) {
        int r1 = row0 + mw * 32 + i * 16 + (lane >> 2);
        int r2 = r1 + 8;
        #pragma unroll
        for (int j = 0; j < 8; j++) {
            int nc = nw * 64 + j * 8 + ((lane & 3) << 1);
            if (r1 < NND) *(float2*)&out[(size_t)r1 * DD + nc] =
                make_float2(acc[i][j][0], acc[i][j][1]);
            if (r2 < NND) *(float2*)&out[(size_t)r2 * DD + nc] =
                make_float2(acc[i][j][2], acc[i][j][3]);
        }
    }
}

// ===================== launch (forked capture: edges ∥ gemm1) ===============
extern "C" void kernel_launch(void* const* d_in, const int* in_sizes, int n_in,
                              void* d_out, int out_size) {
    const float* x  = (const float*)d_in[0];
    const void*  ei = d_in[1];
    const float* Wc = (const float*)d_in[2];
    const float* bc = (const float*)d_in[3];
    const float* W0 = (const float*)d_in[4];
    const float* Wt = (const float*)d_in[5];
    float* out = (float*)d_out;

    const int gemm_blocks = (NND + 127) / 128;   // 391
    const int DSM = 4 * TILEB;                   // 139264 B

    cudaFuncSetAttribute(gemm1_mma, cudaFuncAttributeMaxDynamicSharedMemorySize, DSM);
    cudaFuncSetAttribute(final_mma, cudaFuncAttributeMaxDynamicSharedMemorySize, DSM);

    cudaStream_t s1;
    cudaStreamCreate(&s1);
    cudaEvent_t evA, evB;
    cudaEventCreateWithFlags(&evA, cudaEventDisableTiming);
    cudaEventCreateWithFlags(&evB, cudaEventDisableTiming);

    // stream 0: dtype detect + zero histogram
    detect_kernel<<<(NND + 255) / 256, 256>>>(ei, in_sizes[1]);
    cudaEventRecord(evA, (cudaStream_t)0);

    // chain B (s1): weights prep -> GEMM1 (independent of edges now)
    cudaStreamWaitEvent(s1, evA, 0);
    prep_kernel<<<(DD * DD + 255) / 256, 256, 0, s1>>>(Wc, W0, Wt);
    gemm1_mma<<<gemm_blocks, 256, DSM, s1>>>(x);
    cudaEventRecord(evB, s1);

    // chain A (stream 0): histogram -> offsets -> CSR place
    hist_kernel<<<(NE + 255) / 256, 256>>>(ei);
    alloc_kernel<<<(NND + 255) / 256, 256>>>();
    place_kernel<<<(NE + 255) / 256, 256>>>(ei);

    // join, then gather + final
    cudaStreamWaitEvent((cudaStream_t)0, evB, 0);
    gather_kernel<<<2048, 256>>>();
    final_mma<<<gemm_blocks, 256, DSM>>>(x, bc, out);

    cudaEventDestroy(evA);
    cudaEventDestroy(evB);
    cudaStreamDestroy(s1);
}